// round 2
// baseline (speedup 1.0000x reference)
#include <cuda_runtime.h>
#include <cstdint>
#include <cstddef>

// 64 MB device scratch for the folded weight Weff = W + 2*(B@A), pre-rounded to tf32.
static __device__ float g_Weff[4096ull * 4096ull];

__device__ __forceinline__ unsigned f2tf32(float f) {
    unsigned r;
    asm("cvt.rna.tf32.f32 %0, %1;" : "=r"(r) : "f"(f));
    return r;
}

// ---------------------------------------------------------------------------
// Kernel 1: Weff[o,i] = tf32_round( W[o,i] + 2 * sum_r B[o,r] * A[r,i] )
// Block: 256 threads, tile = 32 o-rows x 128 i-cols. A tile cached in smem.
// ---------------------------------------------------------------------------
__global__ void weff_kernel(const float* __restrict__ W,
                            const float* __restrict__ A,
                            const float* __restrict__ B) {
    __shared__ float As[16][128];
    __shared__ float Bsh[32][16];
    const int o0 = blockIdx.y * 32;
    const int i0 = blockIdx.x * 128;
    const int tid = threadIdx.x;

    // Load A tile [16][128] (512 float4 / 256 threads = 2 each)
    for (int idx = tid; idx < 16 * 32; idx += 256) {
        const int r = idx >> 5, c = idx & 31;
        reinterpret_cast<float4*>(&As[r][0])[c] =
            reinterpret_cast<const float4*>(A + r * 4096 + i0)[c];
    }
    // Load B tile [32][16]
    for (int idx = tid; idx < 32 * 16; idx += 256) {
        const int r = idx >> 4, c = idx & 15;
        Bsh[r][c] = B[(size_t)(o0 + r) * 16 + c];
    }
    __syncthreads();

    const int tx = tid & 31;   // float4 column index
    const int ty = tid >> 5;   // 0..7
    #pragma unroll
    for (int j = 0; j < 4; j++) {
        const int ol = ty + 8 * j;
        const size_t off = (size_t)(o0 + ol) * 4096 + i0;
        const float4 w = reinterpret_cast<const float4*>(W + off)[tx];
        float4 acc = make_float4(0.f, 0.f, 0.f, 0.f);
        #pragma unroll
        for (int r = 0; r < 16; r++) {
            const float br = Bsh[ol][r];
            const float4 a = reinterpret_cast<const float4*>(&As[r][0])[tx];
            acc.x += br * a.x; acc.y += br * a.y;
            acc.z += br * a.z; acc.w += br * a.w;
        }
        uint4 o;
        o.x = f2tf32(w.x + 2.0f * acc.x);
        o.y = f2tf32(w.y + 2.0f * acc.y);
        o.z = f2tf32(w.z + 2.0f * acc.z);
        o.w = f2tf32(w.w + 2.0f * acc.w);
        reinterpret_cast<uint4*>(g_Weff + off)[tx] = o;
    }
}

// ---------------------------------------------------------------------------
// Kernel 2: out[m,n] = sum_k x[m,k] * Weff[n,k] + bias[n]
// TF32 mma.sync m16n8k8. Block tile 128x128x16, 8 warps (2m x 4n),
// warp tile 64x32. Double-buffered smem, padded stride 20 (conflict-free
// fragment loads), register-prefetched global loads, fused bias epilogue.
// ---------------------------------------------------------------------------
__global__ __launch_bounds__(256, 2)
void lora_gemm_kernel(const float* __restrict__ X,
                      const float* __restrict__ bias,
                      float* __restrict__ out) {
    __shared__ unsigned As[2][128][20];  // x tile, tf32 bits, [m][k]
    __shared__ unsigned Bs[2][128][20];  // Weff tile (already tf32), [n][k]

    const int m0 = blockIdx.y << 7;
    const int n0 = blockIdx.x << 7;
    const int tid  = threadIdx.x;
    const int warp = tid >> 5;
    const int lane = tid & 31;
    const int wm  = (warp >> 2) << 6;  // warp m offset: 0 or 64
    const int wn  = (warp & 3) << 5;   // warp n offset: 0,32,64,96
    const int gid = lane >> 2;         // 0..7
    const int tig = lane & 3;          // 0..3

    // Loader mapping: each thread loads 2 float4 per tile per operand.
    const int lrow = tid >> 2;         // 0..63 (and +64)
    const int lk   = (tid & 3) << 2;   // 0,4,8,12

    float c[4][4][4];
    #pragma unroll
    for (int i = 0; i < 4; i++)
        #pragma unroll
        for (int j = 0; j < 4; j++)
            #pragma unroll
            for (int q = 0; q < 4; q++) c[i][j][q] = 0.f;

    const float* xbase = X + (size_t)m0 * 4096;
    const float* wbase = g_Weff + (size_t)n0 * 4096;

    float4 xv[2], wv[2];
    // Prologue: load k-tile 0
    #pragma unroll
    for (int h = 0; h < 2; h++) {
        const size_t ro = (size_t)(lrow + 64 * h) * 4096 + lk;
        xv[h] = *reinterpret_cast<const float4*>(xbase + ro);
        wv[h] = *reinterpret_cast<const float4*>(wbase + ro);
    }
    #pragma unroll
    for (int h = 0; h < 2; h++) {
        const int row = lrow + 64 * h;
        As[0][row][lk + 0] = f2tf32(xv[h].x);
        As[0][row][lk + 1] = f2tf32(xv[h].y);
        As[0][row][lk + 2] = f2tf32(xv[h].z);
        As[0][row][lk + 3] = f2tf32(xv[h].w);
        Bs[0][row][lk + 0] = __float_as_uint(wv[h].x);
        Bs[0][row][lk + 1] = __float_as_uint(wv[h].y);
        Bs[0][row][lk + 2] = __float_as_uint(wv[h].z);
        Bs[0][row][lk + 3] = __float_as_uint(wv[h].w);
    }
    __syncthreads();

    int buf = 0;
    for (int kt = 0; kt < 256; kt++) {
        // Prefetch next k-tile into registers (overlaps with MMA below)
        if (kt < 255) {
            const int knext = (kt + 1) << 4;
            #pragma unroll
            for (int h = 0; h < 2; h++) {
                const size_t ro = (size_t)(lrow + 64 * h) * 4096 + knext + lk;
                xv[h] = *reinterpret_cast<const float4*>(xbase + ro);
                wv[h] = *reinterpret_cast<const float4*>(wbase + ro);
            }
        }
        // Compute on current buffer: 2 k-steps of 8
        #pragma unroll
        for (int ks = 0; ks < 2; ks++) {
            const int k0 = ks << 3;
            unsigned a[4][4], bq[4][2];
            #pragma unroll
            for (int fm = 0; fm < 4; fm++) {
                const int r = wm + (fm << 4) + gid;
                a[fm][0] = As[buf][r][k0 + tig];
                a[fm][1] = As[buf][r + 8][k0 + tig];
                a[fm][2] = As[buf][r][k0 + tig + 4];
                a[fm][3] = As[buf][r + 8][k0 + tig + 4];
            }
            #pragma unroll
            for (int fn = 0; fn < 4; fn++) {
                const int cn = wn + (fn << 3) + gid;
                bq[fn][0] = Bs[buf][cn][k0 + tig];
                bq[fn][1] = Bs[buf][cn][k0 + tig + 4];
            }
            #pragma unroll
            for (int fm = 0; fm < 4; fm++)
                #pragma unroll
                for (int fn = 0; fn < 4; fn++) {
                    asm volatile(
                        "mma.sync.aligned.m16n8k8.row.col.f32.tf32.tf32.f32 "
                        "{%0,%1,%2,%3}, {%4,%5,%6,%7}, {%8,%9}, {%0,%1,%2,%3};"
                        : "+f"(c[fm][fn][0]), "+f"(c[fm][fn][1]),
                          "+f"(c[fm][fn][2]), "+f"(c[fm][fn][3])
                        : "r"(a[fm][0]), "r"(a[fm][1]),
                          "r"(a[fm][2]), "r"(a[fm][3]),
                          "r"(bq[fn][0]), "r"(bq[fn][1]));
                }
        }
        // Stage the prefetched tile into the other buffer, then sync.
        if (kt < 255) {
            const int nb = buf ^ 1;
            #pragma unroll
            for (int h = 0; h < 2; h++) {
                const int row = lrow + 64 * h;
                As[nb][row][lk + 0] = f2tf32(xv[h].x);
                As[nb][row][lk + 1] = f2tf32(xv[h].y);
                As[nb][row][lk + 2] = f2tf32(xv[h].z);
                As[nb][row][lk + 3] = f2tf32(xv[h].w);
                Bs[nb][row][lk + 0] = __float_as_uint(wv[h].x);
                Bs[nb][row][lk + 1] = __float_as_uint(wv[h].y);
                Bs[nb][row][lk + 2] = __float_as_uint(wv[h].z);
                Bs[nb][row][lk + 3] = __float_as_uint(wv[h].w);
            }
            __syncthreads();
            buf = nb;
        }
    }

    // Epilogue: add bias, store fp32.
    #pragma unroll
    for (int fm = 0; fm < 4; fm++) {
        const int r0 = m0 + wm + (fm << 4) + gid;
        #pragma unroll
        for (int fn = 0; fn < 4; fn++) {
            const int col = n0 + wn + (fn << 3) + (tig << 1);
            const float2 bv = *reinterpret_cast<const float2*>(bias + col);
            float2 v0 = make_float2(c[fm][fn][0] + bv.x, c[fm][fn][1] + bv.y);
            float2 v1 = make_float2(c[fm][fn][2] + bv.x, c[fm][fn][3] + bv.y);
            *reinterpret_cast<float2*>(out + (size_t)r0 * 4096 + col) = v0;
            *reinterpret_cast<float2*>(out + (size_t)(r0 + 8) * 4096 + col) = v1;
        }
    }
}

// ---------------------------------------------------------------------------
// Harness entry. Inputs (metadata order): x, W, b, A, B. Output fp32 [8192,4096].
// ---------------------------------------------------------------------------
extern "C" void kernel_launch(void* const* d_in, const int* in_sizes, int n_in,
                              void* d_out, int out_size) {
    const float* x = (const float*)d_in[0];
    const float* W = (const float*)d_in[1];
    const float* b = (const float*)d_in[2];
    const float* A = (const float*)d_in[3];
    const float* B = (const float*)d_in[4];
    float* out = (float*)d_out;

    // Fold LoRA into the weight (tf32-rounded), then one big TF32 GEMM.
    weff_kernel<<<dim3(32, 128), 256>>>(W, A, B);
    lora_gemm_kernel<<<dim3(32, 64), 256>>>(x, b, out);
}

// round 4
// speedup vs baseline: 2.4571x; 2.4571x over previous
#include <cuda_runtime.h>
#include <cuda_fp16.h>
#include <cstdint>
#include <cstddef>

// ---------------------------------------------------------------------------
// Device scratch: fp16-rounded folded weight and fp16-rounded x.
// (fp16 mantissa == tf32 mantissa == 10 bits, so accuracy matches R1's
//  measured rel_err 2.96e-4; fp16 doubles legacy mma rate and halves smem.)
// ---------------------------------------------------------------------------
static __device__ __half g_Wh[4096ull * 4096ull];   // 32 MB
static __device__ __half g_Xh[8192ull * 4096ull];   // 64 MB

__device__ __forceinline__ uint32_t smem_u32(const void* p) {
    uint32_t a;
    asm("{ .reg .u64 t; cvta.to.shared.u64 t, %1; cvt.u32.u64 %0, t; }"
        : "=r"(a) : "l"(p));
    return a;
}

#define CP16(dst, src) \
    asm volatile("cp.async.cg.shared.global [%0], [%1], 16;" \
                 :: "r"(dst), "l"(src) : "memory")
#define CP_COMMIT() asm volatile("cp.async.commit_group;" ::: "memory")
#define CP_WAIT1()  asm volatile("cp.async.wait_group 1;" ::: "memory")

#define LDSM4(r, addr) \
    asm volatile("ldmatrix.sync.aligned.m8n8.x4.shared.b16 {%0,%1,%2,%3}, [%4];" \
                 : "=r"((r)[0]), "=r"((r)[1]), "=r"((r)[2]), "=r"((r)[3]) \
                 : "r"(addr))

#define MMA16816(c, a, b0, b1) \
    asm volatile("mma.sync.aligned.m16n8k16.row.col.f32.f16.f16.f32 " \
                 "{%0,%1,%2,%3},{%4,%5,%6,%7},{%8,%9},{%0,%1,%2,%3};" \
                 : "+f"((c)[0]), "+f"((c)[1]), "+f"((c)[2]), "+f"((c)[3]) \
                 : "r"((a)[0]), "r"((a)[1]), "r"((a)[2]), "r"((a)[3]), \
                   "r"(b0), "r"(b1))

// ---------------------------------------------------------------------------
// Kernel 0: g_Xh = fp16_rn(x).  Each thread: 8 floats -> 16B of halves.
// ---------------------------------------------------------------------------
__global__ void xround_kernel(const float* __restrict__ x) {
    const size_t i = (size_t)blockIdx.x * blockDim.x + threadIdx.x;
    const float4 v0 = reinterpret_cast<const float4*>(x)[2 * i];
    const float4 v1 = reinterpret_cast<const float4*>(x)[2 * i + 1];
    __half2 h[4];
    h[0] = __floats2half2_rn(v0.x, v0.y);
    h[1] = __floats2half2_rn(v0.z, v0.w);
    h[2] = __floats2half2_rn(v1.x, v1.y);
    h[3] = __floats2half2_rn(v1.z, v1.w);
    reinterpret_cast<uint4*>(g_Xh)[i] = *reinterpret_cast<uint4*>(h);
}

// ---------------------------------------------------------------------------
// Kernel 1: g_Wh[o,i] = fp16_rn( W[o,i] + 2 * sum_r B[o,r] * A[r,i] )
// ---------------------------------------------------------------------------
__global__ void weff_kernel(const float* __restrict__ W,
                            const float* __restrict__ A,
                            const float* __restrict__ B) {
    __shared__ float As[16][128];
    __shared__ float Bsh[32][16];
    const int o0 = blockIdx.y * 32;
    const int i0 = blockIdx.x * 128;
    const int tid = threadIdx.x;

    for (int idx = tid; idx < 16 * 32; idx += 256) {
        const int r = idx >> 5, c = idx & 31;
        reinterpret_cast<float4*>(&As[r][0])[c] =
            reinterpret_cast<const float4*>(A + r * 4096 + i0)[c];
    }
    for (int idx = tid; idx < 32 * 16; idx += 256) {
        const int r = idx >> 4, c = idx & 15;
        Bsh[r][c] = B[(size_t)(o0 + r) * 16 + c];
    }
    __syncthreads();

    const int tx = tid & 31;
    const int ty = tid >> 5;
    #pragma unroll
    for (int j = 0; j < 4; j++) {
        const int ol = ty + 8 * j;
        const size_t off = (size_t)(o0 + ol) * 4096 + i0;
        const float4 w = reinterpret_cast<const float4*>(W + off)[tx];
        float4 acc = make_float4(0.f, 0.f, 0.f, 0.f);
        #pragma unroll
        for (int r = 0; r < 16; r++) {
            const float br = Bsh[ol][r];
            const float4 a = reinterpret_cast<const float4*>(&As[r][0])[tx];
            acc.x += br * a.x; acc.y += br * a.y;
            acc.z += br * a.z; acc.w += br * a.w;
        }
        __half2 h0 = __floats2half2_rn(w.x + 2.f * acc.x, w.y + 2.f * acc.y);
        __half2 h1 = __floats2half2_rn(w.z + 2.f * acc.z, w.w + 2.f * acc.w);
        uint2 o;
        o.x = *reinterpret_cast<uint32_t*>(&h0);
        o.y = *reinterpret_cast<uint32_t*>(&h1);
        reinterpret_cast<uint2*>(g_Wh + off)[tx] = o;
    }
}

// ---------------------------------------------------------------------------
// Kernel 2: fp16 tensor GEMM.  out[m,n] = sum_k Xh[m,k]*Wh[n,k] + bias[n]
// CTA tile 128(M) x 256(N) x 64(K)/stage, 3-stage cp.async pipeline.
// 8 warps (2m x 4n), warp tile 64x64. SW128 swizzle, ldmatrix.x4, m16n8k16.
// ---------------------------------------------------------------------------
static constexpr int BK      = 64;                 // halves per stage (128B row)
static constexpr int STAGES  = 3;
static constexpr int A_STAGE = 128 * 128;          // bytes: 128 rows x 128B
static constexpr int B_STAGE = 256 * 128;          // bytes: 256 rows x 128B
static constexpr int SMEM_SZ = STAGES * (A_STAGE + B_STAGE);  // 147456
static constexpr int KT      = 4096 / BK;          // 64

// byte offset of logical (row, 16B-unit c) inside a tile with SW128 swizzle
__device__ __forceinline__ uint32_t sw_off(int row, int c) {
    return (uint32_t)(row * 128 + ((c ^ (row & 7)) << 4));
}

__global__ __launch_bounds__(256, 1)
void gemm_fp16(const float* __restrict__ bias, float* __restrict__ out) {
    extern __shared__ __align__(1024) char smem[];
    const uint32_t sb = smem_u32(smem);
    const uint32_t sA = sb;
    const uint32_t sB = sb + STAGES * A_STAGE;

    const int tid  = threadIdx.x;
    const int lane = tid & 31;
    const int warp = tid >> 5;
    const int wm = (warp >> 2) << 6;   // 0 or 64
    const int wn = (warp & 3) << 6;    // 0,64,128,192
    const int m0 = blockIdx.y << 7;
    const int n0 = blockIdx.x << 8;

    const __half* __restrict__ Xh = g_Xh;
    const __half* __restrict__ Wh = g_Wh;

    float acc[4][8][4];
    #pragma unroll
    for (int i = 0; i < 4; i++)
        #pragma unroll
        for (int j = 0; j < 8; j++)
            #pragma unroll
            for (int q = 0; q < 4; q++) acc[i][j][q] = 0.f;

    auto load_stage = [&](int s, int kt) {
        const int k0 = kt * BK;
        #pragma unroll
        for (int it = 0; it < 4; it++) {          // A: 1024 16B units
            const int u = it * 256 + tid;
            const int row = u >> 3, c = u & 7;
            CP16(sA + s * A_STAGE + sw_off(row, c),
                 Xh + (size_t)(m0 + row) * 4096 + k0 + c * 8);
        }
        #pragma unroll
        for (int it = 0; it < 8; it++) {          // B: 2048 16B units
            const int u = it * 256 + tid;
            const int row = u >> 3, c = u & 7;
            CP16(sB + s * B_STAGE + sw_off(row, c),
                 Wh + (size_t)(n0 + row) * 4096 + k0 + c * 8);
        }
        CP_COMMIT();
    };

    load_stage(0, 0);
    load_stage(1, 1);

    for (int kt = 0; kt < KT; kt++) {
        CP_WAIT1();
        __syncthreads();
        if (kt + 2 < KT) load_stage((kt + 2) % STAGES, kt + 2);
        else             CP_COMMIT();

        const int buf = kt % STAGES;
        const uint32_t ab = sA + buf * A_STAGE;
        const uint32_t bb = sB + buf * B_STAGE;
        const int arow = lane & 15;
        const int aclo = lane >> 4;

        #pragma unroll
        for (int q = 0; q < 4; q++) {             // 4 k16-chunks
            uint32_t ar[4][4], br[4][4];
            #pragma unroll
            for (int fm = 0; fm < 4; fm++)
                LDSM4(ar[fm], ab + sw_off(wm + fm * 16 + arow, q * 2 + aclo));
            #pragma unroll
            for (int j = 0; j < 4; j++)
                LDSM4(br[j], bb + sw_off(wn + j * 16 + arow, q * 2 + aclo));
            #pragma unroll
            for (int fm = 0; fm < 4; fm++)
                #pragma unroll
                for (int j = 0; j < 4; j++) {
                    MMA16816(acc[fm][2 * j],     ar[fm], br[j][0], br[j][2]);
                    MMA16816(acc[fm][2 * j + 1], ar[fm], br[j][1], br[j][3]);
                }
        }
    }

    // Epilogue: direct reg -> gmem with fused bias.
    #pragma unroll
    for (int fm = 0; fm < 4; fm++) {
        const int r0 = m0 + wm + fm * 16 + (lane >> 2);
        #pragma unroll
        for (int fn = 0; fn < 8; fn++) {
            const int col = n0 + wn + fn * 8 + ((lane & 3) << 1);
            const float2 b2 = *reinterpret_cast<const float2*>(bias + col);
            float2 v0 = make_float2(acc[fm][fn][0] + b2.x, acc[fm][fn][1] + b2.y);
            float2 v1 = make_float2(acc[fm][fn][2] + b2.x, acc[fm][fn][3] + b2.y);
            *reinterpret_cast<float2*>(out + (size_t)r0 * 4096 + col) = v0;
            *reinterpret_cast<float2*>(out + (size_t)(r0 + 8) * 4096 + col) = v1;
        }
    }
}

// ---------------------------------------------------------------------------
// Host entry. Inputs: x, W, b, A, B. Output fp32 [8192, 4096].
// ---------------------------------------------------------------------------
extern "C" void kernel_launch(void* const* d_in, const int* in_sizes, int n_in,
                              void* d_out, int out_size) {
    const float* x = (const float*)d_in[0];
    const float* W = (const float*)d_in[1];
    const float* b = (const float*)d_in[2];
    const float* A = (const float*)d_in[3];
    const float* B = (const float*)d_in[4];
    float* out = (float*)d_out;

    static bool attr_done = false;
    if (!attr_done) {
        cudaFuncSetAttribute(gemm_fp16,
                             cudaFuncAttributeMaxDynamicSharedMemorySize, SMEM_SZ);
        attr_done = true;
    }

    xround_kernel<<<8192 * 4096 / 8 / 256, 256>>>(x);
    weff_kernel<<<dim3(32, 128), 256>>>(W, A, B);
    gemm_fp16<<<dim3(16, 64), 256, SMEM_SZ>>>(b, out);
}